// round 9
// baseline (speedup 1.0000x reference)
#include <cuda_runtime.h>

#define N 1024
#define H 96
#define E 16384

// ---------------- scratch (device globals; no allocation allowed) ----------
__device__ float g_bufA[N*H];
__device__ float g_bufB[N*H];
__device__ float g_m[N*H];
__device__ int   g_hist[N];            // zero at load; re-zeroed by k_att(mode1)
__device__ int   g_off[N+1];
__device__ int   g_cur[N];
__device__ float g_hi[N*H];            // pre-scaled by 0.5
__device__ float g_hjb[N*H];           // pre-scaled by 0.5, includes ba1
__device__ int   g_src[E];
__device__ int   g_tgt[E];
__device__ int   g_esrc[E];            // CSR payload (src per target-sorted slot)
__device__ unsigned short g_list[N*N]; // compacted active-j per row (sorted asc)
__device__ int   g_rcnt[N];
__device__ float g_WgT4[96*576];       // gate weights [k/4][c][4]; c<288: Wih else Whh
__device__ float g_WfT4[96*192];       // feature weights [k/4][c][4]; c<96: Wai else Waj
__device__ float g_Wo1T[96*96];
__device__ float g_Wo2T[96*96];

__device__ __forceinline__ float tanha(float v){
    float t; asm("tanh.approx.f32 %0, %1;" : "=f"(t) : "f"(v)); return t;
}
__device__ __forceinline__ float sigt(float v){        // 1-MUFU sigmoid
    return fmaf(0.5f, tanha(0.5f*v), 0.5f);
}
__device__ __forceinline__ float sig_acc(float v){     // accurate (final outputs)
    float e; asm("ex2.approx.f32 %0, %1;" : "=f"(e) : "f"(v * -1.4426950408889634f));
    float r; asm("rcp.approx.f32 %0, %1;" : "=f"(r) : "f"(1.0f + e));
    return r;
}
__device__ __forceinline__ float leaky(float v){
    return (v >= 0.0f) ? v : 0.01f * v;
}

// ---- 1. prep: fused float4 weight layouts + head transposes + decode -------
__global__ void k_pre(const float* __restrict__ Wih, const float* __restrict__ Whh,
                      const float* __restrict__ Wa1,
                      const float* __restrict__ Wo1, const float* __restrict__ Wo2,
                      const int* __restrict__ ei32){
    int t = blockIdx.x * 256 + threadIdx.x;   // < 55296
    {   // gate weights -> [k/4][c][4]
        int k = t / 576, c = t - k*576;
        float v = (c < 288) ? Wih[c*96 + k] : Whh[(c-288)*96 + k];
        g_WgT4[(k >> 2)*2304 + c*4 + (k & 3)] = v;
    }
    if (t < 96*192){   // feature weights -> [k/4][c][4]
        int k = t / 192, c = t - k*192;
        float v = (c < 96) ? Wa1[c*192 + k] : Wa1[(c-96)*192 + 96 + k];
        g_WfT4[(k >> 2)*768 + c*4 + (k & 3)] = v;
    }
    if (t < 96*96){
        int h = t / 96, k = t - h*96;
        g_Wo1T[k*96 + h] = Wo1[t];
        g_Wo2T[k*96 + h] = Wo2[t];
    }
    if (t < E){
        int odd_or = 0;
        #pragma unroll
        for (int q = 0; q < 16; q++) odd_or |= ei32[2*q + 1];
        int s, tt;
        if (odd_or == 0){ s = ei32[2*t];  tt = ei32[2*(E + t)]; }  // int64 layout
        else            { s = ei32[t];    tt = ei32[E + t];     }  // int32 layout
        if ((unsigned)s >= N || (unsigned)tt >= N){ s = -1; tt = -1; }
        g_src[t] = s;
        g_tgt[t] = tt;
        if (tt >= 0) atomicAdd(&g_hist[tt], 1);
    }
}

// ---- 2. exclusive scan of histogram -> CSR offsets + cursors ---------------
__global__ void k_scan(){
    __shared__ int sc[1024];
    int t = threadIdx.x;
    int v = g_hist[t];
    sc[t] = v;
    __syncthreads();
    for (int o = 1; o < 1024; o <<= 1){
        int add = (t >= o) ? sc[t - o] : 0;
        __syncthreads();
        sc[t] += add;
        __syncthreads();
    }
    int excl = sc[t] - v;
    g_off[t] = excl;
    g_cur[t] = excl;
    if (t == 1023) g_off[1024] = sc[1023];
}

// ---- 3. CSR fill (blocks 0..63) + init & first m=x@Wg (blocks 64..319) -----
__global__ __launch_bounds__(384) void k_fi(const float* __restrict__ xin,
                      const float* __restrict__ Wi, const float* __restrict__ bi,
                      const float* __restrict__ Wg){
    int b = blockIdx.x;
    if (b < 64){
        if (threadIdx.x < 256){
            int e = b*256 + threadIdx.x;
            int tt = g_tgt[e];
            if (tt >= 0){
                int pos = atomicAdd(&g_cur[tt], 1);
                g_esrc[pos] = g_src[e];
            }
        }
        return;
    }
    int bb = b - 64;
    int r = threadIdx.x / 96, h = threadIdx.x % 96;
    int n = bb*4 + r;
    __shared__ float xr[4][10], xs[4][96];
    if (threadIdx.x < 40){
        int rr = threadIdx.x / 10, c = threadIdx.x % 10;
        xr[rr][c] = xin[(bb*4 + rr)*10 + c];
    }
    __syncthreads();
    float a = bi[h];
    #pragma unroll
    for (int k = 0; k < 9; k++) a = fmaf(xr[r][k], Wi[h*9 + k], a);
    float xv = leaky(a);
    g_bufA[n*96 + h] = xv;
    xs[r][h] = xv;
    __syncthreads();
    float a0 = 0.f, a1 = 0.f;
    #pragma unroll 8
    for (int k = 0; k < 96; k += 2){
        a0 = fmaf(xs[r][k],   Wg[k*96 + h],     a0);
        a1 = fmaf(xs[r][k+1], Wg[(k+1)*96 + h], a1);
    }
    g_m[n*96 + h] = a0 + a1;
}

// ---- 4. compact adjacency rows (preloaded, ballot scan) --------------------
__global__ void k_rows(const int* __restrict__ adj){
    int warp = threadIdx.x >> 5, lane = threadIdx.x & 31;
    int row = blockIdx.x * 8 + warp;
    const int* arow = adj + row * N;
    int av[32];
    #pragma unroll
    for (int w = 0; w < 32; w++) av[w] = arow[w*32 + lane];
    int base = 0;
    #pragma unroll
    for (int w = 0; w < 32; w++){
        unsigned m = __ballot_sync(0xffffffffu, av[w] == 1);
        if (av[w] == 1){
            int pos = base + __popc(m & ((1u << lane) - 1u));
            g_list[row*N + pos] = (unsigned short)(w*32 + lane);
        }
        base += __popc(m);
    }
    if (lane == 0) g_rcnt[row] = base;
}

// ---- 5/7. GRU: 4 nodes/block, 576 threads, float4 weight loads -------------
__global__ __launch_bounds__(576) void k_gru(int srcbuf,
                      const float* __restrict__ bih, const float* __restrict__ bhh,
                      const float* __restrict__ ba1){
    float* x = srcbuf ? g_bufB : g_bufA;
    int tid = threadIdx.x;
    int nb = blockIdx.x * 4;
    __shared__ __align__(16) float ag[4][96], xr[4][96], xn[4][96];
    __shared__ float dot[4][576];            // gate dots; reused as feature partials

    // --- CSR gather: one thread per (node, h) slot + x load ---
    if (tid < 384){
        int r = tid / 96, h = tid - r*96;
        int n = nb + r;
        int o0 = g_off[n], o1 = g_off[n+1];
        float s0 = 0.f, s1 = 0.f;
        int p = o0;
        for (; p + 2 <= o1; p += 2){
            s0 += g_m[g_esrc[p]*96 + h];
            s1 += g_m[g_esrc[p+1]*96 + h];
        }
        if (p < o1) s0 += g_m[g_esrc[p]*96 + h];
        float inv;
        asm("rcp.approx.f32 %0, %1;" : "=f"(inv) : "f"(fmaxf((float)(o1 - o0), 1.0f)));
        ag[r][h] = (s0 + s1) * inv;
        xr[r][h] = x[n*96 + h];
    }
    __syncthreads();

    // --- 6 gate dots, thread = column c, 4 nodes, float4 k-chunks ---
    {
        int c = tid;
        bool isI = c < 288;
        float bias = isI ? bih[c] : bhh[c - 288];
        const float* opb = isI ? &ag[0][0] : &xr[0][0];
        const float4* W4 = (const float4*)g_WgT4;
        float d0 = bias, d1 = bias, d2 = bias, d3 = bias;
        #pragma unroll 6
        for (int k4 = 0; k4 < 24; k4++){
            float4 w  = W4[k4*576 + c];
            float4 p0 = *((const float4*)(opb)       + k4);
            float4 p1 = *((const float4*)(opb + 96)  + k4);
            float4 p2 = *((const float4*)(opb + 192) + k4);
            float4 p3 = *((const float4*)(opb + 288) + k4);
            d0 = fmaf(w.x, p0.x, d0); d0 = fmaf(w.y, p0.y, d0);
            d0 = fmaf(w.z, p0.z, d0); d0 = fmaf(w.w, p0.w, d0);
            d1 = fmaf(w.x, p1.x, d1); d1 = fmaf(w.y, p1.y, d1);
            d1 = fmaf(w.z, p1.z, d1); d1 = fmaf(w.w, p1.w, d1);
            d2 = fmaf(w.x, p2.x, d2); d2 = fmaf(w.y, p2.y, d2);
            d2 = fmaf(w.z, p2.z, d2); d2 = fmaf(w.w, p2.w, d2);
            d3 = fmaf(w.x, p3.x, d3); d3 = fmaf(w.y, p3.y, d3);
            d3 = fmaf(w.z, p3.z, d3); d3 = fmaf(w.w, p3.w, d3);
        }
        dot[0][c] = d0; dot[1][c] = d1; dot[2][c] = d2; dot[3][c] = d3;
    }
    __syncthreads();

    // --- gate combination ---
    if (tid < 384){
        int r = tid / 96, h = tid - r*96;
        float rg = sigt(dot[r][h]        + dot[r][288 + h]);
        float zg = sigt(dot[r][96 + h]   + dot[r][384 + h]);
        float ng = tanha(dot[r][192 + h] + rg * dot[r][480 + h]);
        float xv = (1.0f - zg) * ng + zg * xr[r][h];
        xn[r][h] = xv;
        x[(nb + r)*96 + h] = xv;
    }
    __syncthreads();

    // --- attention features: thread = (k-slice s of 32, col c), 4 nodes -----
    {
        int s = tid / 192, c = tid - s*192;
        const float4* Wf4 = (const float4*)g_WfT4;
        float f0 = 0.f, f1 = 0.f, f2 = 0.f, f3 = 0.f;
        #pragma unroll 8
        for (int k4 = s*8; k4 < s*8 + 8; k4++){
            float4 w  = Wf4[k4*192 + c];
            float4 q0 = ((const float4*)xn[0])[k4];
            float4 q1 = ((const float4*)xn[1])[k4];
            float4 q2 = ((const float4*)xn[2])[k4];
            float4 q3 = ((const float4*)xn[3])[k4];
            f0 = fmaf(w.x, q0.x, f0); f0 = fmaf(w.y, q0.y, f0);
            f0 = fmaf(w.z, q0.z, f0); f0 = fmaf(w.w, q0.w, f0);
            f1 = fmaf(w.x, q1.x, f1); f1 = fmaf(w.y, q1.y, f1);
            f1 = fmaf(w.z, q1.z, f1); f1 = fmaf(w.w, q1.w, f1);
            f2 = fmaf(w.x, q2.x, f2); f2 = fmaf(w.y, q2.y, f2);
            f2 = fmaf(w.z, q2.z, f2); f2 = fmaf(w.w, q2.w, f2);
            f3 = fmaf(w.x, q3.x, f3); f3 = fmaf(w.y, q3.y, f3);
            f3 = fmaf(w.z, q3.z, f3); f3 = fmaf(w.w, q3.w, f3);
        }
        dot[0][s*192 + c] = f0;
        dot[1][s*192 + c] = f1;
        dot[2][s*192 + c] = f2;
        dot[3][s*192 + c] = f3;
    }
    __syncthreads();
    for (int s = tid; s < 768; s += 576){
        int r = s / 192, c = s - r*192;
        float val = dot[r][c] + dot[r][192 + c] + dot[r][384 + c];
        int n = nb + r;
        if (c < 96) g_hi[n*96 + c] = 0.5f * val;
        else        g_hjb[n*96 + (c - 96)] = 0.5f * (val + ba1[c - 96]);
    }
}

// ---- 6/8. attention: 2 rows x 6 warps, 2-pair ILP, 384 threads -------------
__global__ __launch_bounds__(384) void k_att(int mode,
                      const float* __restrict__ Wa2, const float* __restrict__ ba2,
                      const float* __restrict__ Wg,
                      const float* __restrict__ bo1, const float* __restrict__ bo2,
                      const float* __restrict__ Wp1, const float* __restrict__ bp1,
                      const float* __restrict__ Wp2, const float* __restrict__ bp2,
                      float* __restrict__ out){
    const float* x = mode ? g_bufB : g_bufA;
    float* xout    = g_bufB;
    int i0 = blockIdx.x * 2;
    int tid = threadIdx.x, wid = tid >> 5, lane = tid & 31;
    int wrow = wid / 6, wsub = wid - wrow*6;     // 6 warps per row, 2 rows
    int irow = i0 + wrow;

    float w0 = 0.5f*Wa2[lane], w1 = 0.5f*Wa2[lane+32], w2 = 0.5f*Wa2[lane+64];
    float hi0 = g_hi[irow*96 + lane];
    float hi1 = g_hi[irow*96 + lane + 32];
    float hi2 = g_hi[irow*96 + lane + 64];
    float ws = w0 + w1 + w2;
    #pragma unroll
    for (int o = 16; o; o >>= 1) ws += __shfl_xor_sync(0xffffffffu, ws, o);
    float bbp = ba2[0] + ws;

    int cnt = g_rcnt[irow];
    const ushort2* lst2 = (const ushort2*)(g_list + irow*N);
    float acc0 = 0.f, acc1 = 0.f, acc2 = 0.f;

    for (int p2 = wsub; p2*2 < cnt; p2 += 6){
        ushort2 js = lst2[p2];
        int p = p2 * 2;
        bool v1 = (p + 1) < cnt;
        int j0 = js.x;
        int j1 = v1 ? (int)js.y : j0;
        const float* h0p = g_hjb + j0*96;
        const float* h1p = g_hjb + j1*96;
        float s0 =      w0 * tanha(hi0 + h0p[lane]);
        float s1 =      w0 * tanha(hi0 + h1p[lane]);
        s0 = fmaf(w1, tanha(hi1 + h0p[lane+32]), s0);
        s1 = fmaf(w1, tanha(hi1 + h1p[lane+32]), s1);
        s0 = fmaf(w2, tanha(hi2 + h0p[lane+64]), s0);
        s1 = fmaf(w2, tanha(hi2 + h1p[lane+64]), s1);
        #pragma unroll
        for (int o = 16; o; o >>= 1){
            s0 += __shfl_xor_sync(0xffffffffu, s0, o);
            s1 += __shfl_xor_sync(0xffffffffu, s1, o);
        }
        float c0 = fmaf(0.5f, tanha(0.5f*(s0 + bbp)), 0.5f);
        float c1 = v1 ? fmaf(0.5f, tanha(0.5f*(s1 + bbp)), 0.5f) : 0.f;
        const float* x0p = x + j0*96;
        const float* x1p = x + j1*96;
        acc0 = fmaf(c0, x0p[lane],    acc0);
        acc1 = fmaf(c0, x0p[lane+32], acc1);
        acc2 = fmaf(c0, x0p[lane+64], acc2);
        acc0 = fmaf(c1, x1p[lane],    acc0);
        acc1 = fmaf(c1, x1p[lane+32], acc1);
        acc2 = fmaf(c1, x1p[lane+64], acc2);
    }

    __shared__ float accs[12][96];
    accs[wid][lane]    = acc0;
    accs[wid][lane+32] = acc1;
    accs[wid][lane+64] = acc2;
    __syncthreads();

    __shared__ float xs[2][96], x1s[2][96];
    int rB = tid / 96, hB = tid - rB*96;        // valid for tid < 192
    if (tid < 192){
        float xv = accs[rB*6][hB]   + accs[rB*6+1][hB] + accs[rB*6+2][hB]
                 + accs[rB*6+3][hB] + accs[rB*6+4][hB] + accs[rB*6+5][hB];
        xs[rB][hB] = xv;
    }
    __syncthreads();

    if (mode == 0){
        if (tid < 192){
            float xv = xs[rB][hB];
            xout[(i0 + rB)*96 + hB] = xv;
            float a0 = 0.f, a1 = 0.f;
            #pragma unroll 8
            for (int k = 0; k < 96; k += 2){
                a0 = fmaf(xs[rB][k],   Wg[k*96 + hB],     a0);
                a1 = fmaf(xs[rB][k+1], Wg[(k+1)*96 + hB], a1);
            }
            g_m[(i0 + rB)*96 + hB] = a0 + a1;
        }
    } else {
        if (tid < 192){
            float a = bo1[hB];
            #pragma unroll 4
            for (int k = 0; k < 96; k++) a = fmaf(xs[rB][k], g_Wo1T[k*96 + hB], a);
            x1s[rB][hB] = leaky(a);
        }
        __syncthreads();
        __shared__ float sw1[6], sw2[6];
        if (tid < 192){
            float b = bo2[hB];
            #pragma unroll 4
            for (int k = 0; k < 96; k++) b = fmaf(x1s[rB][k], g_Wo2T[k*96 + hB], b);
            float v = leaky(b);
            float r1 = v * Wp1[hB];
            float r2 = v * Wp2[hB];
            #pragma unroll
            for (int o = 16; o; o >>= 1){
                r1 += __shfl_xor_sync(0xffffffffu, r1, o);
                r2 += __shfl_xor_sync(0xffffffffu, r2, o);
            }
            if (lane == 0){ sw1[wid] = r1; sw2[wid] = r2; }
        }
        __syncthreads();
        if (tid < 192 && hB == 0){
            int n = i0 + rB;
            out[n]     = sig_acc(sw1[rB*3] + sw1[rB*3+1] + sw1[rB*3+2] + bp1[0]);
            out[N + n] = sig_acc(sw2[rB*3] + sw2[rB*3+1] + sw2[rB*3+2] + bp2[0]);
            g_hist[n] = 0;   // reset for next replay
        }
    }
}

// ---------------- launch -----------------------------------------------------
extern "C" void kernel_launch(void* const* d_in, const int* in_sizes, int n_in,
                              void* d_out, int out_size){
    const float* x_in  = (const float*)d_in[0];
    const int*   ei32  = (const int*)d_in[1];
    const int*   adj   = (const int*)d_in[2];
    const float* W_init= (const float*)d_in[3];
    const float* b_init= (const float*)d_in[4];
    const float* W_ggc = (const float*)d_in[5];
    const float* W_ih  = (const float*)d_in[6];
    const float* W_hh  = (const float*)d_in[7];
    const float* b_ih  = (const float*)d_in[8];
    const float* b_hh  = (const float*)d_in[9];
    const float* Wa1   = (const float*)d_in[10];
    const float* ba1   = (const float*)d_in[11];
    const float* Wa2   = (const float*)d_in[12];
    const float* ba2   = (const float*)d_in[13];
    const float* Wo1   = (const float*)d_in[14];
    const float* bo1   = (const float*)d_in[15];
    const float* Wo2   = (const float*)d_in[16];
    const float* bo2   = (const float*)d_in[17];
    const float* Wp1   = (const float*)d_in[18];
    const float* bp1   = (const float*)d_in[19];
    const float* Wp2   = (const float*)d_in[20];
    const float* bp2   = (const float*)d_in[21];
    float* out = (float*)d_out;

    k_pre<<<216, 256>>>(W_ih, W_hh, Wa1, Wo1, Wo2, ei32);               // 1
    k_scan<<<1, 1024>>>();                                              // 2
    k_fi<<<320, 384>>>(x_in, W_init, b_init, W_ggc);                    // 3
    k_rows<<<N/8, 256>>>(adj);                                          // 4
    k_gru<<<N/4, 576>>>(0, b_ih, b_hh, ba1);                            // 5
    k_att<<<N/2, 384>>>(0, Wa2, ba2, W_ggc, bo1, bo2, Wp1, bp1, Wp2, bp2, out); // 6 (profiled)
    k_gru<<<N/4, 576>>>(1, b_ih, b_hh, ba1);                            // 7
    k_att<<<N/2, 384>>>(1, Wa2, ba2, W_ggc, bo1, bo2, Wp1, bp1, Wp2, bp2, out); // 8
}

// round 10
// speedup vs baseline: 1.7035x; 1.7035x over previous
#include <cuda_runtime.h>

#define N 1024
#define H 96
#define E 16384

// ---------------- scratch (device globals; no allocation allowed) ----------
__device__ float g_bufA[N*H];
__device__ float g_bufB[N*H];
__device__ float g_m[N*H];
__device__ int   g_hist[N];            // zero at load; re-zeroed by k_att(mode1)
__device__ int   g_off[N+1];
__device__ int   g_cur[N];
__device__ float g_hi[N*H];            // pre-scaled by 0.5
__device__ float g_hjb[N*H];           // pre-scaled by 0.5, includes ba1
__device__ int   g_src[E];
__device__ int   g_tgt[E];
__device__ int   g_esrc[E];            // CSR payload (src per target-sorted slot)
__device__ unsigned short g_list[N*N]; // compacted active-j per row (sorted asc)
__device__ int   g_rcnt[N];
__device__ float g_WgT[96*576];        // fused gate weights [k][c]; c<288: Wih, else Whh
__device__ float g_WfT[96*192];        // fused feature weights [k][c]; c<96: Wai, else Waj
__device__ float g_Wo1T[96*96];
__device__ float g_Wo2T[96*96];

__device__ __forceinline__ float tanha(float v){
    float t; asm("tanh.approx.f32 %0, %1;" : "=f"(t) : "f"(v)); return t;
}
__device__ __forceinline__ float sigt(float v){        // 1-MUFU sigmoid
    return fmaf(0.5f, tanha(0.5f*v), 0.5f);
}
__device__ __forceinline__ float sig_acc(float v){     // accurate (final outputs)
    float e; asm("ex2.approx.f32 %0, %1;" : "=f"(e) : "f"(v * -1.4426950408889634f));
    float r; asm("rcp.approx.f32 %0, %1;" : "=f"(r) : "f"(1.0f + e));
    return r;
}
__device__ __forceinline__ float leaky(float v){
    return (v >= 0.0f) ? v : 0.01f * v;
}

// ---- 1. prep: fused weight layouts + head transposes + decode + adj rows ---
__global__ void k_pre(const float* __restrict__ Wih, const float* __restrict__ Whh,
                      const float* __restrict__ Wa1,
                      const float* __restrict__ Wo1, const float* __restrict__ Wo2,
                      const int* __restrict__ ei32, const int* __restrict__ adj){
    if (blockIdx.x >= 216){
        // ---- adjacency row compaction (8 rows per block, ballot scan) ----
        int warp = threadIdx.x >> 5, lane = threadIdx.x & 31;
        int row = (blockIdx.x - 216) * 8 + warp;
        const int* arow = adj + row * N;
        int av[32];
        #pragma unroll
        for (int w = 0; w < 32; w++) av[w] = arow[w*32 + lane];
        int base = 0;
        #pragma unroll
        for (int w = 0; w < 32; w++){
            unsigned m = __ballot_sync(0xffffffffu, av[w] == 1);
            if (av[w] == 1){
                int pos = base + __popc(m & ((1u << lane) - 1u));
                g_list[row*N + pos] = (unsigned short)(w*32 + lane);
            }
            base += __popc(m);
        }
        if (lane == 0) g_rcnt[row] = base;
        return;
    }
    int t = blockIdx.x * 256 + threadIdx.x;   // < 55296
    {   // fused gate weights
        int k = t / 576, c = t - k*576;
        g_WgT[t] = (c < 288) ? Wih[c*96 + k] : Whh[(c-288)*96 + k];
    }
    if (t < 96*192){
        int k = t / 192, c = t - k*192;
        g_WfT[t] = (c < 96) ? Wa1[c*192 + k] : Wa1[(c-96)*192 + 96 + k];
    }
    if (t < 96*96){
        int h = t / 96, k = t - h*96;
        g_Wo1T[k*96 + h] = Wo1[t];
        g_Wo2T[k*96 + h] = Wo2[t];
    }
    if (t < E){
        int odd_or = 0;
        #pragma unroll
        for (int q = 0; q < 16; q++) odd_or |= ei32[2*q + 1];
        int s, tt;
        if (odd_or == 0){ s = ei32[2*t];  tt = ei32[2*(E + t)]; }  // int64 layout
        else            { s = ei32[t];    tt = ei32[E + t];     }  // int32 layout
        if ((unsigned)s >= N || (unsigned)tt >= N){ s = -1; tt = -1; }
        g_src[t] = s;
        g_tgt[t] = tt;
        if (tt >= 0) atomicAdd(&g_hist[tt], 1);
    }
}

// ---- 2. exclusive scan of histogram -> CSR offsets + cursors ---------------
__global__ void k_scan(){
    __shared__ int sc[1024];
    int t = threadIdx.x;
    int v = g_hist[t];
    sc[t] = v;
    __syncthreads();
    for (int o = 1; o < 1024; o <<= 1){
        int add = (t >= o) ? sc[t - o] : 0;
        __syncthreads();
        sc[t] += add;
        __syncthreads();
    }
    int excl = sc[t] - v;
    g_off[t] = excl;
    g_cur[t] = excl;
    if (t == 1023) g_off[1024] = sc[1023];
}

// ---- 3. CSR fill (blocks 0..63) + init & first m=x@Wg (blocks 64..319) -----
__global__ __launch_bounds__(384) void k_fi(const float* __restrict__ xin,
                      const float* __restrict__ Wi, const float* __restrict__ bi,
                      const float* __restrict__ Wg){
    int b = blockIdx.x;
    if (b < 64){
        if (threadIdx.x < 256){
            int e = b*256 + threadIdx.x;
            int tt = g_tgt[e];
            if (tt >= 0){
                int pos = atomicAdd(&g_cur[tt], 1);
                g_esrc[pos] = g_src[e];
            }
        }
        return;
    }
    int bb = b - 64;
    int r = threadIdx.x / 96, h = threadIdx.x % 96;
    int n = bb*4 + r;
    __shared__ float xr[4][10], xs[4][96];
    if (threadIdx.x < 40){
        int rr = threadIdx.x / 10, c = threadIdx.x % 10;
        xr[rr][c] = xin[(bb*4 + rr)*10 + c];
    }
    __syncthreads();
    float a = bi[h];
    #pragma unroll
    for (int k = 0; k < 9; k++) a = fmaf(xr[r][k], Wi[h*9 + k], a);
    float xv = leaky(a);
    g_bufA[n*96 + h] = xv;
    xs[r][h] = xv;
    __syncthreads();
    float a0 = 0.f, a1 = 0.f;
    #pragma unroll 8
    for (int k = 0; k < 96; k += 2){
        a0 = fmaf(xs[r][k],   Wg[k*96 + h],     a0);
        a1 = fmaf(xs[r][k+1], Wg[(k+1)*96 + h], a1);
    }
    g_m[n*96 + h] = a0 + a1;
}

// ---- 4/6. GRU: 4 nodes/block, 576 threads (thread = output column) ---------
__global__ __launch_bounds__(576) void k_gru(int srcbuf,
                      const float* __restrict__ bih, const float* __restrict__ bhh,
                      const float* __restrict__ ba1){
    float* x = srcbuf ? g_bufB : g_bufA;
    int tid = threadIdx.x;
    int nb = blockIdx.x * 4;
    __shared__ float ag[4][96], xr[4][96], xn[4][96];
    __shared__ float dot[4][576];            // gate dots; reused as feature partials

    // --- CSR gather: one thread per (node, h) slot + x load ---
    if (tid < 384){
        int r = tid / 96, h = tid - r*96;
        int n = nb + r;
        int o0 = g_off[n], o1 = g_off[n+1];
        float s0 = 0.f, s1 = 0.f;
        int p = o0;
        for (; p + 2 <= o1; p += 2){
            s0 += g_m[g_esrc[p]*96 + h];
            s1 += g_m[g_esrc[p+1]*96 + h];
        }
        if (p < o1) s0 += g_m[g_esrc[p]*96 + h];
        float inv;
        asm("rcp.approx.f32 %0, %1;" : "=f"(inv) : "f"(fmaxf((float)(o1 - o0), 1.0f)));
        ag[r][h] = (s0 + s1) * inv;
        xr[r][h] = x[n*96 + h];
    }
    __syncthreads();

    // --- 6 gate dots, thread = column c, 4 nodes per thread ---
    {
        int c = tid;
        bool isI = c < 288;
        float bias = isI ? bih[c] : bhh[c - 288];
        const float (*op)[96] = isI ? ag : xr;
        float d0 = bias, d1 = bias, d2 = bias, d3 = bias;
        #pragma unroll 8
        for (int k = 0; k < 96; k++){
            float w = g_WgT[k*576 + c];
            d0 = fmaf(w, op[0][k], d0);
            d1 = fmaf(w, op[1][k], d1);
            d2 = fmaf(w, op[2][k], d2);
            d3 = fmaf(w, op[3][k], d3);
        }
        dot[0][c] = d0; dot[1][c] = d1; dot[2][c] = d2; dot[3][c] = d3;
    }
    __syncthreads();

    // --- gate combination ---
    if (tid < 384){
        int r = tid / 96, h = tid - r*96;
        float rg = sigt(dot[r][h]        + dot[r][288 + h]);
        float zg = sigt(dot[r][96 + h]   + dot[r][384 + h]);
        float ng = tanha(dot[r][192 + h] + rg * dot[r][480 + h]);
        float xv = (1.0f - zg) * ng + zg * xr[r][h];
        xn[r][h] = xv;
        x[(nb + r)*96 + h] = xv;
    }
    __syncthreads();

    // --- attention features: thread = (k-slice s of 32, column c), 4 nodes ---
    {
        int s = tid / 192, c = tid - s*192;
        float f0 = 0.f, f1 = 0.f, f2 = 0.f, f3 = 0.f;
        int k0 = s * 32;
        #pragma unroll 8
        for (int k = k0; k < k0 + 32; k++){
            float w = g_WfT[k*192 + c];
            f0 = fmaf(w, xn[0][k], f0);
            f1 = fmaf(w, xn[1][k], f1);
            f2 = fmaf(w, xn[2][k], f2);
            f3 = fmaf(w, xn[3][k], f3);
        }
        dot[0][s*192 + c] = f0;
        dot[1][s*192 + c] = f1;
        dot[2][s*192 + c] = f2;
        dot[3][s*192 + c] = f3;
    }
    __syncthreads();
    for (int s = tid; s < 768; s += 576){
        int r = s / 192, c = s - r*192;
        float val = dot[r][c] + dot[r][192 + c] + dot[r][384 + c];
        int n = nb + r;
        if (c < 96) g_hi[n*96 + c] = 0.5f * val;
        else        g_hjb[n*96 + (c - 96)] = 0.5f * (val + ba1[c - 96]);
    }
}

// ---- 5/7. attention (6 warps/row, 4 rows, 4-pair ILP, hoisted x loads) -----
__global__ __launch_bounds__(768) void k_att(int mode,
                      const float* __restrict__ Wa2, const float* __restrict__ ba2,
                      const float* __restrict__ Wg,
                      const float* __restrict__ bo1, const float* __restrict__ bo2,
                      const float* __restrict__ Wp1, const float* __restrict__ bp1,
                      const float* __restrict__ Wp2, const float* __restrict__ bp2,
                      float* __restrict__ out){
    const float* x = mode ? g_bufB : g_bufA;
    float* xout    = g_bufB;
    int i0 = blockIdx.x * 4;
    int tid = threadIdx.x, wid = tid >> 5, lane = tid & 31;
    int wrow = wid / 6, wsub = wid - wrow*6;     // 6 warps per row
    int irow = i0 + wrow;

    float w0 = 0.5f*Wa2[lane], w1 = 0.5f*Wa2[lane+32], w2 = 0.5f*Wa2[lane+64];
    float hi0 = g_hi[irow*96 + lane];
    float hi1 = g_hi[irow*96 + lane + 32];
    float hi2 = g_hi[irow*96 + lane + 64];
    float ws = w0 + w1 + w2;
    #pragma unroll
    for (int o = 16; o; o >>= 1) ws += __shfl_xor_sync(0xffffffffu, ws, o);
    float bbp = ba2[0] + ws;

    int cnt = g_rcnt[irow];
    const ushort4* lst4 = (const ushort4*)(g_list + irow*N);
    float acc0 = 0.f, acc1 = 0.f, acc2 = 0.f;

    for (int p4 = wsub; p4*4 < cnt; p4 += 6){
        ushort4 js = lst4[p4];                    // one 8B load, 4 indices
        int p = p4 * 4;
        bool v1 = (p + 1) < cnt, v2 = (p + 2) < cnt, v3 = (p + 3) < cnt;
        int j0 = js.x;
        int j1 = v1 ? (int)js.y : j0;
        int j2 = v2 ? (int)js.z : j0;
        int j3 = v3 ? (int)js.w : j0;
        const float* h0p = g_hjb + j0*96;
        const float* h1p = g_hjb + j1*96;
        const float* h2p = g_hjb + j2*96;
        const float* h3p = g_hjb + j3*96;
        const float* x0p = x + j0*96;
        const float* x1p = x + j1*96;
        const float* x2p = x + j2*96;
        const float* x3p = x + j3*96;
        // --- hoist ALL 24 loads so they are in flight during the shuffle chain
        float xa0 = x0p[lane], xa1 = x0p[lane+32], xa2 = x0p[lane+64];
        float xb0 = x1p[lane], xb1 = x1p[lane+32], xb2 = x1p[lane+64];
        float xc0 = x2p[lane], xc1 = x2p[lane+32], xc2 = x2p[lane+64];
        float xd0 = x3p[lane], xd1 = x3p[lane+32], xd2 = x3p[lane+64];
        float s0 =      w0 * tanha(hi0 + h0p[lane]);
        float s1 =      w0 * tanha(hi0 + h1p[lane]);
        float s2 =      w0 * tanha(hi0 + h2p[lane]);
        float s3 =      w0 * tanha(hi0 + h3p[lane]);
        s0 = fmaf(w1, tanha(hi1 + h0p[lane+32]), s0);
        s1 = fmaf(w1, tanha(hi1 + h1p[lane+32]), s1);
        s2 = fmaf(w1, tanha(hi1 + h2p[lane+32]), s2);
        s3 = fmaf(w1, tanha(hi1 + h3p[lane+32]), s3);
        s0 = fmaf(w2, tanha(hi2 + h0p[lane+64]), s0);
        s1 = fmaf(w2, tanha(hi2 + h1p[lane+64]), s1);
        s2 = fmaf(w2, tanha(hi2 + h2p[lane+64]), s2);
        s3 = fmaf(w2, tanha(hi2 + h3p[lane+64]), s3);
        #pragma unroll
        for (int o = 16; o; o >>= 1){
            s0 += __shfl_xor_sync(0xffffffffu, s0, o);
            s1 += __shfl_xor_sync(0xffffffffu, s1, o);
            s2 += __shfl_xor_sync(0xffffffffu, s2, o);
            s3 += __shfl_xor_sync(0xffffffffu, s3, o);
        }
        float c0 = fmaf(0.5f, tanha(0.5f*(s0 + bbp)), 0.5f);
        float c1 = v1 ? fmaf(0.5f, tanha(0.5f*(s1 + bbp)), 0.5f) : 0.f;
        float c2 = v2 ? fmaf(0.5f, tanha(0.5f*(s2 + bbp)), 0.5f) : 0.f;
        float c3 = v3 ? fmaf(0.5f, tanha(0.5f*(s3 + bbp)), 0.5f) : 0.f;
        acc0 = fmaf(c0, xa0, acc0);
        acc1 = fmaf(c0, xa1, acc1);
        acc2 = fmaf(c0, xa2, acc2);
        acc0 = fmaf(c1, xb0, acc0);
        acc1 = fmaf(c1, xb1, acc1);
        acc2 = fmaf(c1, xb2, acc2);
        acc0 = fmaf(c2, xc0, acc0);
        acc1 = fmaf(c2, xc1, acc1);
        acc2 = fmaf(c2, xc2, acc2);
        acc0 = fmaf(c3, xd0, acc0);
        acc1 = fmaf(c3, xd1, acc1);
        acc2 = fmaf(c3, xd2, acc2);
    }

    __shared__ float accs[24][96];
    accs[wid][lane]    = acc0;
    accs[wid][lane+32] = acc1;
    accs[wid][lane+64] = acc2;
    __syncthreads();

    __shared__ float xs[4][96], x1s[4][96];
    int rB = tid / 96, hB = tid - rB*96;        // valid for tid < 384
    if (tid < 384){
        float xv = accs[rB*6][hB]   + accs[rB*6+1][hB] + accs[rB*6+2][hB]
                 + accs[rB*6+3][hB] + accs[rB*6+4][hB] + accs[rB*6+5][hB];
        xs[rB][hB] = xv;
    }
    __syncthreads();

    if (mode == 0){
        if (tid < 384){
            float xv = xs[rB][hB];
            xout[(i0 + rB)*96 + hB] = xv;
            float a0 = 0.f, a1 = 0.f;
            #pragma unroll 8
            for (int k = 0; k < 96; k += 2){
                a0 = fmaf(xs[rB][k],   Wg[k*96 + hB],     a0);
                a1 = fmaf(xs[rB][k+1], Wg[(k+1)*96 + hB], a1);
            }
            g_m[(i0 + rB)*96 + hB] = a0 + a1;
        }
    } else {
        if (tid < 384){
            float a = bo1[hB];
            #pragma unroll 4
            for (int k = 0; k < 96; k++) a = fmaf(xs[rB][k], g_Wo1T[k*96 + hB], a);
            x1s[rB][hB] = leaky(a);
        }
        __syncthreads();
        __shared__ float sw1[12], sw2[12];
        if (tid < 384){
            float b = bo2[hB];
            #pragma unroll 4
            for (int k = 0; k < 96; k++) b = fmaf(x1s[rB][k], g_Wo2T[k*96 + hB], b);
            float v = leaky(b);
            float r1 = v * Wp1[hB];
            float r2 = v * Wp2[hB];
            #pragma unroll
            for (int o = 16; o; o >>= 1){
                r1 += __shfl_xor_sync(0xffffffffu, r1, o);
                r2 += __shfl_xor_sync(0xffffffffu, r2, o);
            }
            if (lane == 0){ sw1[wid] = r1; sw2[wid] = r2; }
        }
        __syncthreads();
        if (tid < 384 && hB == 0){
            int n = i0 + rB;
            out[n]     = sig_acc(sw1[rB*3] + sw1[rB*3+1] + sw1[rB*3+2] + bp1[0]);
            out[N + n] = sig_acc(sw2[rB*3] + sw2[rB*3+1] + sw2[rB*3+2] + bp2[0]);
            g_hist[n] = 0;   // reset for next replay
        }
    }
}

// ---------------- launch -----------------------------------------------------
extern "C" void kernel_launch(void* const* d_in, const int* in_sizes, int n_in,
                              void* d_out, int out_size){
    const float* x_in  = (const float*)d_in[0];
    const int*   ei32  = (const int*)d_in[1];
    const int*   adj   = (const int*)d_in[2];
    const float* W_init= (const float*)d_in[3];
    const float* b_init= (const float*)d_in[4];
    const float* W_ggc = (const float*)d_in[5];
    const float* W_ih  = (const float*)d_in[6];
    const float* W_hh  = (const float*)d_in[7];
    const float* b_ih  = (const float*)d_in[8];
    const float* b_hh  = (const float*)d_in[9];
    const float* Wa1   = (const float*)d_in[10];
    const float* ba1   = (const float*)d_in[11];
    const float* Wa2   = (const float*)d_in[12];
    const float* ba2   = (const float*)d_in[13];
    const float* Wo1   = (const float*)d_in[14];
    const float* bo1   = (const float*)d_in[15];
    const float* Wo2   = (const float*)d_in[16];
    const float* bo2   = (const float*)d_in[17];
    const float* Wp1   = (const float*)d_in[18];
    const float* bp1   = (const float*)d_in[19];
    const float* Wp2   = (const float*)d_in[20];
    const float* bp2   = (const float*)d_in[21];
    float* out = (float*)d_out;

    k_pre<<<216 + 128, 256>>>(W_ih, W_hh, Wa1, Wo1, Wo2, ei32, adj);    // 1
    k_scan<<<1, 1024>>>();                                              // 2
    k_fi<<<320, 384>>>(x_in, W_init, b_init, W_ggc);                    // 3
    k_gru<<<N/4, 576>>>(0, b_ih, b_hh, ba1);                            // 4 (profiled)
    k_att<<<N/4, 768>>>(0, Wa2, ba2, W_ggc, bo1, bo2, Wp1, bp1, Wp2, bp2, out); // 5
    k_gru<<<N/4, 576>>>(1, b_ih, b_hh, ba1);                            // 6
    k_att<<<N/4, 768>>>(1, Wa2, ba2, W_ggc, bo1, bo2, Wp1, bp1, Wp2, bp2, out); // 7
}